// round 6
// baseline (speedup 1.0000x reference)
#include <cuda_runtime.h>
#include <cuda_bf16.h>
#include <cstdint>

#define NSEQ 2048
#define DIN  1024
#define DOUT 1024
#define BATCH 8
#define NTOK  (BATCH * NSEQ)   // 16384

// ---------------- device scratch (no allocations allowed) ----------------
__device__ float g_S[(size_t)BATCH * NSEQ * NSEQ];
__device__ __nv_bfloat16 g_Xhi[(size_t)NTOK * DIN];
__device__ __nv_bfloat16 g_Xlo[(size_t)NTOK * DIN];
__device__ __nv_bfloat16 g_Wt_hi[3ull * DOUT * DIN];
__device__ __nv_bfloat16 g_Wt_lo[3ull * DOUT * DIN];
__device__ __nv_bfloat16 g_Qhi[(size_t)NTOK * DOUT];
__device__ __nv_bfloat16 g_Qlo[(size_t)NTOK * DOUT];
__device__ __nv_bfloat16 g_Khi[(size_t)NTOK * DOUT];
__device__ __nv_bfloat16 g_Klo[(size_t)NTOK * DOUT];
__device__ __nv_bfloat16 g_Vt_hi[(size_t)BATCH * DOUT * NSEQ];
__device__ __nv_bfloat16 g_Vt_lo[(size_t)BATCH * DOUT * NSEQ];
__device__ __nv_bfloat16 g_Phi[(size_t)BATCH * NSEQ * NSEQ];
__device__ __nv_bfloat16 g_Plo[(size_t)BATCH * NSEQ * NSEQ];

// ---------------- helpers ----------------
__device__ __forceinline__ uint32_t smem_u32(const void* p) {
    uint32_t a;
    asm("{ .reg .u64 t; cvta.to.shared.u64 t, %1; cvt.u32.u64 %0, t; }" : "=r"(a) : "l"(p));
    return a;
}
__device__ __forceinline__ void ldm_x4(uint32_t r[4], uint32_t addr) {
    asm volatile("ldmatrix.sync.aligned.m8n8.x4.shared.b16 {%0,%1,%2,%3}, [%4];"
                 : "=r"(r[0]), "=r"(r[1]), "=r"(r[2]), "=r"(r[3]) : "r"(addr));
}
__device__ __forceinline__ void mma16816(float* c, const uint32_t* a, const uint32_t* b) {
    asm volatile(
        "mma.sync.aligned.m16n8k16.row.col.f32.bf16.bf16.f32 "
        "{%0,%1,%2,%3}, {%4,%5,%6,%7}, {%8,%9}, {%0,%1,%2,%3};"
        : "+f"(c[0]), "+f"(c[1]), "+f"(c[2]), "+f"(c[3])
        : "r"(a[0]), "r"(a[1]), "r"(a[2]), "r"(a[3]), "r"(b[0]), "r"(b[1]));
}
#define CP16(dst, src) \
    asm volatile("cp.async.cg.shared.global [%0], [%1], 16;" :: "r"(dst), "l"(src))
#define CPCOMMIT() asm volatile("cp.async.commit_group;" ::: "memory")
#define CPWAIT1()  asm volatile("cp.async.wait_group 1;" ::: "memory")
#define CPWAIT0()  asm volatile("cp.async.wait_group 0;" ::: "memory")

__device__ __forceinline__ uint32_t pack2(__nv_bfloat16 a, __nv_bfloat16 b) {
    return (uint32_t)__bfloat16_as_ushort(a) | ((uint32_t)__bfloat16_as_ushort(b) << 16);
}
__device__ __forceinline__ void split2c(float x, float y, uint32_t& hp, uint32_t& lp) {
    __nv_bfloat16 hx = __float2bfloat16_rn(x), hy = __float2bfloat16_rn(y);
    __nv_bfloat16 lx = __float2bfloat16_rn(x - __bfloat162float(hx));
    __nv_bfloat16 ly = __float2bfloat16_rn(y - __bfloat162float(hy));
    hp = pack2(hx, hy);
    lp = pack2(lx, ly);
}

// ---------------- tile geometry ----------------
// CTA 256(M) x 256(N) x BK=32. 512 threads, 16 warps as 4(M) x 4(N),
// warp tile 64x64. SMEM rows 80 B -> conflict-free ldmatrix.
#define BM 256
#define BN 256
#define NTHREADS 512
#define TTB (256 * 80)           // 20480 bytes per tile
#define OFF_ALO TTB
#define OFF_BHI (2 * TTB)
#define OFF_BLO (3 * TTB)
#define STG (4 * TTB)            // 81920 per stage
#define SMEM_SZ (2 * STG)        // 163840

// cp.async one hi/lo tile pair (256 rows x 32 bf16) into stage SMEM
__device__ __forceinline__ void stage_load(
    uint32_t sHi, const __nv_bfloat16* __restrict__ hi,
    const __nv_bfloat16* __restrict__ lo, int ld, int base, int k0, int tid)
{
#pragma unroll
    for (int i = 0; i < 2; i++) {
        int idx = tid + i * NTHREADS;      // 1024 chunks
        int row = idx >> 2;
        int c   = idx & 3;
        size_t g = (size_t)(base + row) * ld + k0 + c * 8;
        uint32_t d = sHi + row * 80 + c * 16;
        CP16(d, hi + g);
        CP16(d + TTB, lo + g);
    }
}

// ---------------- core GEMM: pre-split bf16, 3-product fp32 emulation ----
// EMODE: 0 = fp32 C, 1 = split+transposed V^T, 2 = split row-major (Q/K)
template <int EMODE>
__device__ __forceinline__ void gemm_ps(
    const __nv_bfloat16* __restrict__ AhiG, const __nv_bfloat16* __restrict__ AloG,
    int lda, int aBase,
    const __nv_bfloat16* __restrict__ BhiG, const __nv_bfloat16* __restrict__ BloG,
    int ldb, int bBase, int kEnd,
    float* __restrict__ C, int ldOut, int oRow, int oCol,
    __nv_bfloat16* __restrict__ OHi, __nv_bfloat16* __restrict__ OLo)
{
    extern __shared__ char smem[];
    const int tid  = threadIdx.x;
    const int wid  = tid >> 5;
    const int lane = tid & 31;
    const int warpM = (wid >> 2) * 64;   // 4 warps in M
    const int warpN = (wid & 3) * 64;    // 4 warps in N
    const int ksFirst = wid & 1;         // stagger: odd warps do ks=1 first

    const uint32_t sb = smem_u32(smem);
    const uint32_t stB[2] = { sb, sb + STG };

    const uint32_t aOff = (uint32_t)(warpM + (lane & 15)) * 80 + ((lane >> 4) << 4);
    const uint32_t bOff = (uint32_t)(warpN + (lane & 7) + ((lane & 16) >> 1)) * 80 +
                          ((lane & 8) << 1);

    float acc[4][8][4];
#pragma unroll
    for (int i = 0; i < 4; i++)
#pragma unroll
        for (int j = 0; j < 8; j++)
#pragma unroll
            for (int e = 0; e < 4; e++) acc[i][j][e] = 0.0f;

    // prologue
    stage_load(stB[0],           AhiG, AloG, lda, aBase, 0, tid);
    stage_load(stB[0] + OFF_BHI, BhiG, BloG, ldb, bBase, 0, tid);
    CPCOMMIT();

    const int NC = kEnd >> 5;
    for (int c = 0; c < NC; c++) {
        const int st = c & 1;
        if (c + 1 < NC) {
            const int k0 = (c + 1) << 5;
            stage_load(stB[st ^ 1],           AhiG, AloG, lda, aBase, k0, tid);
            stage_load(stB[st ^ 1] + OFF_BHI, BhiG, BloG, ldb, bBase, k0, tid);
            CPCOMMIT();
            CPWAIT1();
        } else {
            CPWAIT0();
        }
        __syncthreads();

        const uint32_t aHiB = stB[st],           aLoB = stB[st] + OFF_ALO;
        const uint32_t bHiB = stB[st] + OFF_BHI, bLoB = stB[st] + OFF_BLO;
#pragma unroll
        for (int t = 0; t < 2; t++) {
            const int ks = ksFirst ^ t;
            const uint32_t ko = (uint32_t)ks * 32;

            uint32_t ah[4][4], al[4][4];
#pragma unroll
            for (int mi = 0; mi < 4; mi++) {
                uint32_t off = aOff + (uint32_t)mi * (16 * 80) + ko;
                ldm_x4(ah[mi], aHiB + off);
                ldm_x4(al[mi], aLoB + off);
            }
            uint32_t bh[8][2], bl[8][2];
#pragma unroll
            for (int n2 = 0; n2 < 4; n2++) {
                uint32_t off = bOff + (uint32_t)n2 * (16 * 80) + ko;
                uint32_t r[4];
                ldm_x4(r, bHiB + off);
                bh[n2 * 2][0] = r[0]; bh[n2 * 2][1] = r[1];
                bh[n2 * 2 + 1][0] = r[2]; bh[n2 * 2 + 1][1] = r[3];
                ldm_x4(r, bLoB + off);
                bl[n2 * 2][0] = r[0]; bl[n2 * 2][1] = r[1];
                bl[n2 * 2 + 1][0] = r[2]; bl[n2 * 2 + 1][1] = r[3];
            }
            // product-major: 32 independent MMAs between accumulator reuse
#pragma unroll
            for (int mi = 0; mi < 4; mi++)
#pragma unroll
                for (int ni = 0; ni < 8; ni++)
                    mma16816(acc[mi][ni], ah[mi], bh[ni]);
#pragma unroll
            for (int mi = 0; mi < 4; mi++)
#pragma unroll
                for (int ni = 0; ni < 8; ni++)
                    mma16816(acc[mi][ni], ah[mi], bl[ni]);
#pragma unroll
            for (int mi = 0; mi < 4; mi++)
#pragma unroll
                for (int ni = 0; ni < 8; ni++)
                    mma16816(acc[mi][ni], al[mi], bh[ni]);
        }
        __syncthreads();
    }

    // ---------------- epilogue ----------------
    const int mBase = warpM + (lane >> 2);
    const int nBase = warpN + (lane & 3) * 2;
    if (EMODE == 0) {
#pragma unroll
        for (int mi = 0; mi < 4; mi++)
#pragma unroll
            for (int ni = 0; ni < 8; ni++) {
                const float* cp = acc[mi][ni];
                int r0 = oRow + mBase + mi * 16;
                int cc = oCol + nBase + ni * 8;
                *(float2*)&C[(size_t)r0 * ldOut + cc]       = make_float2(cp[0], cp[1]);
                *(float2*)&C[(size_t)(r0 + 8) * ldOut + cc] = make_float2(cp[2], cp[3]);
            }
    } else if (EMODE == 2) {
#pragma unroll
        for (int mi = 0; mi < 4; mi++)
#pragma unroll
            for (int ni = 0; ni < 8; ni++) {
                const float* cp = acc[mi][ni];
#pragma unroll
                for (int h = 0; h < 2; h++) {
                    int r0 = oRow + mBase + mi * 16 + h * 8;
                    int cc = oCol + nBase + ni * 8;
                    uint32_t hp, lp;
                    split2c(cp[h * 2], cp[h * 2 + 1], hp, lp);
                    *(uint32_t*)&OHi[(size_t)r0 * ldOut + cc] = hp;
                    *(uint32_t*)&OLo[(size_t)r0 * ldOut + cc] = lp;
                }
            }
    } else {
        // V^T split: (seq=row, e=col) -> Vt[b][e][seq]
#pragma unroll
        for (int mi = 0; mi < 4; mi++)
#pragma unroll
            for (int ni = 0; ni < 8; ni++) {
                const float* cp = acc[mi][ni];
#pragma unroll
                for (int e = 0; e < 4; e++) {
                    int row = oRow + mBase + mi * 16 + (e >> 1) * 8;
                    int col = oCol + nBase + ni * 8 + (e & 1);
                    int b = row >> 11, nloc = row & (NSEQ - 1);
                    float x = cp[e];
                    __nv_bfloat16 hh = __float2bfloat16_rn(x);
                    __nv_bfloat16 ll = __float2bfloat16_rn(x - __bfloat162float(hh));
                    size_t o = ((size_t)b * DOUT + col) * NSEQ + nloc;
                    OHi[o] = hh;
                    OLo[o] = ll;
                }
            }
    }
}

// ---------------- kernels ----------------

__global__ void __launch_bounds__(256) xsplit_kernel(const float* __restrict__ X)
{
    size_t i4 = (size_t)blockIdx.x * 256 + threadIdx.x;
    float4 v = *(const float4*)&X[i4 * 4];
    uint32_t h0, h1, l0, l1;
    split2c(v.x, v.y, h0, l0);
    split2c(v.z, v.w, h1, l1);
    *(uint2*)&g_Xhi[i4 * 4] = make_uint2(h0, h1);
    *(uint2*)&g_Xlo[i4 * 4] = make_uint2(l0, l1);
}

__global__ void __launch_bounds__(256) wsplit_kernel(
    const float* __restrict__ Wq, const float* __restrict__ Wk, const float* __restrict__ Wv)
{
    const int z = blockIdx.z;
    const float* W = (z == 0) ? Wq : (z == 1) ? Wk : Wv;
    __nv_bfloat16* H = g_Wt_hi + (size_t)z * DOUT * DIN;
    __nv_bfloat16* L = g_Wt_lo + (size_t)z * DOUT * DIN;

    __shared__ float t[32][33];
    const int j0 = blockIdx.x * 32;
    const int i0 = blockIdx.y * 32;
    const int tx = threadIdx.x & 31, ty = threadIdx.x >> 5;
#pragma unroll
    for (int k = 0; k < 4; k++)
        t[ty + k * 8][tx] = W[(size_t)(i0 + ty + k * 8) * DOUT + j0 + tx];
    __syncthreads();
#pragma unroll
    for (int k = 0; k < 4; k++) {
        float x = t[tx][ty + k * 8];
        __nv_bfloat16 h = __float2bfloat16_rn(x);
        __nv_bfloat16 l = __float2bfloat16_rn(x - __bfloat162float(h));
        size_t o = (size_t)(j0 + ty + k * 8) * DIN + i0 + tx;
        H[o] = h;
        L[o] = l;
    }
}

// QKV: z=0 -> Q split, z=1 -> K split, z=2 -> V^T split
__global__ void __launch_bounds__(NTHREADS, 1) qkv_kernel()
{
    const int z = blockIdx.z;
    const __nv_bfloat16* bh = g_Wt_hi + (size_t)z * DOUT * DIN;
    const __nv_bfloat16* bl = g_Wt_lo + (size_t)z * DOUT * DIN;
    const int rowBase = blockIdx.y * BM;
    const int colBase = blockIdx.x * BN;
    if (z == 2)
        gemm_ps<1>(g_Xhi, g_Xlo, DIN, rowBase, bh, bl, DIN, colBase, DIN,
                   nullptr, 0, rowBase, colBase, g_Vt_hi, g_Vt_lo);
    else if (z == 0)
        gemm_ps<2>(g_Xhi, g_Xlo, DIN, rowBase, bh, bl, DIN, colBase, DIN,
                   nullptr, DOUT, rowBase, colBase, g_Qhi, g_Qlo);
    else
        gemm_ps<2>(g_Xhi, g_Xlo, DIN, rowBase, bh, bl, DIN, colBase, DIN,
                   nullptr, DOUT, rowBase, colBase, g_Khi, g_Klo);
}

// Scores: 256x256 tiles; skip fully-masked tiles (kT > qT).
__global__ void __launch_bounds__(NTHREADS, 1) score_kernel()
{
    const int b = blockIdx.z, qT = blockIdx.y, kT = blockIdx.x;
    if (kT > qT) return;
    gemm_ps<0>(g_Qhi, g_Qlo, DOUT, b * NSEQ + qT * BM,
               g_Khi, g_Klo, DOUT, b * NSEQ + kT * BN, DOUT,
               g_S + (size_t)b * NSEQ * NSEQ, NSEQ, qT * BM, kT * BN,
               nullptr, nullptr);
}

// Causal softmax; writes pre-split bf16 P zero-filled to 256-aligned boundary.
__global__ void __launch_bounds__(256) softmax_kernel()
{
    const int row = blockIdx.x;
    const int b = row >> 11;
    const int q = row & (NSEQ - 1);
    const size_t rb = (size_t)b * NSEQ * NSEQ + (size_t)q * NSEQ;
    const float* s = g_S + rb;

    const int len = q + 1;
    const int alignedOut = (len + 255) & ~255;   // PV reads 256-row granular

    float v[8];
    float m = -1e30f;
#pragma unroll
    for (int i = 0; i < 2; i++) {
        int base = (threadIdx.x + i * 256) * 4;
        if (base < alignedOut) {
            float4 x = *(const float4*)&s[base];
            v[i * 4 + 0] = (base + 0 < len) ? x.x * 0.03125f : -1e30f;
            v[i * 4 + 1] = (base + 1 < len) ? x.y * 0.03125f : -1e30f;
            v[i * 4 + 2] = (base + 2 < len) ? x.z * 0.03125f : -1e30f;
            v[i * 4 + 3] = (base + 3 < len) ? x.w * 0.03125f : -1e30f;
        } else {
            v[i * 4] = v[i * 4 + 1] = v[i * 4 + 2] = v[i * 4 + 3] = -1e30f;
        }
#pragma unroll
        for (int e = 0; e < 4; e++) m = fmaxf(m, v[i * 4 + e]);
    }

    __shared__ float red[256];
    red[threadIdx.x] = m;
    __syncthreads();
#pragma unroll
    for (int off = 128; off > 0; off >>= 1) {
        if (threadIdx.x < off)
            red[threadIdx.x] = fmaxf(red[threadIdx.x], red[threadIdx.x + off]);
        __syncthreads();
    }
    m = red[0];
    __syncthreads();

    float sum = 0.0f;
#pragma unroll
    for (int i = 0; i < 8; i++) {
        float e = __expf(v[i] - m);
        v[i] = e;
        sum += e;
    }
    red[threadIdx.x] = sum;
    __syncthreads();
#pragma unroll
    for (int off = 128; off > 0; off >>= 1) {
        if (threadIdx.x < off)
            red[threadIdx.x] += red[threadIdx.x + off];
        __syncthreads();
    }
    const float inv = 1.0f / red[0];

#pragma unroll
    for (int i = 0; i < 2; i++) {
        int base = (threadIdx.x + i * 256) * 4;
        if (base < alignedOut) {
            float p0 = v[i * 4] * inv, p1 = v[i * 4 + 1] * inv;
            float p2 = v[i * 4 + 2] * inv, p3 = v[i * 4 + 3] * inv;
            uint32_t h0, h1, l0, l1;
            split2c(p0, p1, h0, l0);
            split2c(p2, p3, h1, l1);
            *(uint2*)&g_Phi[rb + base] = make_uint2(h0, h1);
            *(uint2*)&g_Plo[rb + base] = make_uint2(l0, l1);
        }
    }
}

// context = P V, causal K extent.
__global__ void __launch_bounds__(NTHREADS, 1) pv_kernel(float* __restrict__ out)
{
    const int b = blockIdx.z, qT = blockIdx.y;
    gemm_ps<0>(g_Phi, g_Plo, NSEQ, b * NSEQ + qT * BM,
               g_Vt_hi, g_Vt_lo, NSEQ, b * DOUT + blockIdx.x * BN,
               (qT + 1) * BM,
               out + (size_t)b * NSEQ * DOUT, DOUT, qT * BM, blockIdx.x * BN,
               nullptr, nullptr);
}

// ---------------- launch ----------------
extern "C" void kernel_launch(void* const* d_in, const int* in_sizes, int n_in,
                              void* d_out, int out_size)
{
    (void)in_sizes; (void)n_in; (void)out_size;
    const float* x  = (const float*)d_in[0];
    const float* Wq = (const float*)d_in[1];
    const float* Wk = (const float*)d_in[2];
    const float* Wv = (const float*)d_in[3];
    float* out = (float*)d_out;

    cudaFuncSetAttribute(qkv_kernel,   cudaFuncAttributeMaxDynamicSharedMemorySize, SMEM_SZ);
    cudaFuncSetAttribute(score_kernel, cudaFuncAttributeMaxDynamicSharedMemorySize, SMEM_SZ);
    cudaFuncSetAttribute(pv_kernel,    cudaFuncAttributeMaxDynamicSharedMemorySize, SMEM_SZ);

    xsplit_kernel<<<NTOK * DIN / 1024, 256>>>(x);
    wsplit_kernel<<<dim3(32, 32, 3), 256>>>(Wq, Wk, Wv);
    qkv_kernel<<<dim3(DOUT / BN, NTOK / BM, 3), NTHREADS, SMEM_SZ>>>();
    score_kernel<<<dim3(NSEQ / BN, NSEQ / BM, BATCH), NTHREADS, SMEM_SZ>>>();
    softmax_kernel<<<BATCH * NSEQ, 256>>>();
    pv_kernel<<<dim3(DOUT / BN, NSEQ / BM, BATCH), NTHREADS, SMEM_SZ>>>(out);
}

// round 7
// speedup vs baseline: 2.0816x; 2.0816x over previous
#include <cuda_runtime.h>
#include <cuda_bf16.h>
#include <cstdint>

#define NSEQ 2048
#define DIN  1024
#define DOUT 1024
#define BATCH 8
#define NTOK  (BATCH * NSEQ)   // 16384

// ---------------- device scratch (no allocations allowed) ----------------
__device__ float g_S[(size_t)BATCH * NSEQ * NSEQ];
__device__ __nv_bfloat16 g_Xhi[(size_t)NTOK * DIN];
__device__ __nv_bfloat16 g_Xlo[(size_t)NTOK * DIN];
__device__ __nv_bfloat16 g_Wt_hi[3ull * DOUT * DIN];
__device__ __nv_bfloat16 g_Wt_lo[3ull * DOUT * DIN];
__device__ __nv_bfloat16 g_Qhi[(size_t)NTOK * DOUT];
__device__ __nv_bfloat16 g_Qlo[(size_t)NTOK * DOUT];
__device__ __nv_bfloat16 g_Khi[(size_t)NTOK * DOUT];
__device__ __nv_bfloat16 g_Klo[(size_t)NTOK * DOUT];
__device__ __nv_bfloat16 g_Vt_hi[(size_t)BATCH * DOUT * NSEQ];
__device__ __nv_bfloat16 g_Vt_lo[(size_t)BATCH * DOUT * NSEQ];
__device__ __nv_bfloat16 g_Phi[(size_t)BATCH * NSEQ * NSEQ];
__device__ __nv_bfloat16 g_Plo[(size_t)BATCH * NSEQ * NSEQ];

// ---------------- helpers ----------------
__device__ __forceinline__ uint32_t smem_u32(const void* p) {
    uint32_t a;
    asm("{ .reg .u64 t; cvta.to.shared.u64 t, %1; cvt.u32.u64 %0, t; }" : "=r"(a) : "l"(p));
    return a;
}
__device__ __forceinline__ void ldm_x4(uint32_t r[4], uint32_t addr) {
    asm volatile("ldmatrix.sync.aligned.m8n8.x4.shared.b16 {%0,%1,%2,%3}, [%4];"
                 : "=r"(r[0]), "=r"(r[1]), "=r"(r[2]), "=r"(r[3]) : "r"(addr));
}
__device__ __forceinline__ void mma16816(float* c, const uint32_t* a, const uint32_t* b) {
    asm volatile(
        "mma.sync.aligned.m16n8k16.row.col.f32.bf16.bf16.f32 "
        "{%0,%1,%2,%3}, {%4,%5,%6,%7}, {%8,%9}, {%0,%1,%2,%3};"
        : "+f"(c[0]), "+f"(c[1]), "+f"(c[2]), "+f"(c[3])
        : "r"(a[0]), "r"(a[1]), "r"(a[2]), "r"(a[3]), "r"(b[0]), "r"(b[1]));
}
#define CP16(dst, src) \
    asm volatile("cp.async.cg.shared.global [%0], [%1], 16;" :: "r"(dst), "l"(src))
#define CPCOMMIT() asm volatile("cp.async.commit_group;" ::: "memory")
#define CPWAIT1()  asm volatile("cp.async.wait_group 1;" ::: "memory")
#define CPWAIT0()  asm volatile("cp.async.wait_group 0;" ::: "memory")

__device__ __forceinline__ uint32_t pack2(__nv_bfloat16 a, __nv_bfloat16 b) {
    return (uint32_t)__bfloat16_as_ushort(a) | ((uint32_t)__bfloat16_as_ushort(b) << 16);
}
__device__ __forceinline__ void split2c(float x, float y, uint32_t& hp, uint32_t& lp) {
    __nv_bfloat16 hx = __float2bfloat16_rn(x), hy = __float2bfloat16_rn(y);
    __nv_bfloat16 lx = __float2bfloat16_rn(x - __bfloat162float(hx));
    __nv_bfloat16 ly = __float2bfloat16_rn(y - __bfloat162float(hy));
    hp = pack2(hx, hy);
    lp = pack2(lx, ly);
}

// SMEM tile: 128 rows x 32 k bf16, 80B row stride (conflict-free ldmatrix).
#define TBYTES   10240            // one tile
#define STG      40960            // 4 tiles per stage
#define SMEM_SZ  (2 * STG)        // 81920 B -> 2 CTAs/SM

// issue cp.async for one hi/lo tile pair (128x32) into stage SMEM
__device__ __forceinline__ void stage_load(
    uint32_t sHi, const __nv_bfloat16* __restrict__ hi,
    const __nv_bfloat16* __restrict__ lo, int ld, int base, int k0, int tid)
{
#pragma unroll
    for (int i = 0; i < 2; i++) {
        int idx = tid + i * 256;           // 512 chunks per tile
        int row = idx >> 2;
        int c   = idx & 3;                 // 16B chunk within row
        size_t g = (size_t)(base + row) * ld + k0 + c * 8;
        uint32_t d = sHi + row * 80 + c * 16;
        CP16(d, hi + g);
        CP16(d + TBYTES, lo + g);
    }
}

// ---------------- core GEMM: all operands pre-split bf16 ----------------
// 128x128 CTA tile, 8 warps (2M x 4N), warp tile 64x32, BK=32.
// EMODE: 0 = fp32 C, 1 = split+transposed V^T, 2 = split row-major (Q/K)
template <int EMODE>
__device__ __forceinline__ void gemm_ps(
    const __nv_bfloat16* __restrict__ AhiG, const __nv_bfloat16* __restrict__ AloG,
    int lda, int aBase,
    const __nv_bfloat16* __restrict__ BhiG, const __nv_bfloat16* __restrict__ BloG,
    int ldb, int bBase, int kEnd,
    float* __restrict__ C, int ldOut, int oRow, int oCol,
    __nv_bfloat16* __restrict__ OHi, __nv_bfloat16* __restrict__ OLo)
{
    extern __shared__ char smem[];
    const int tid  = threadIdx.x;
    const int wid  = tid >> 5;
    const int lane = tid & 31;
    const int warpM = (wid >> 2) * 64;
    const int warpN = (wid & 3) * 32;
    const int ksFirst = wid & 1;         // stagger: odd warps do ks=1 first

    const uint32_t sb = smem_u32(smem);
    const uint32_t stB[2] = { sb, sb + STG };

    const uint32_t aOff = (uint32_t)(warpM + (lane & 15)) * 80 + ((lane >> 4) << 4);
    const uint32_t bOff = (uint32_t)(warpN + (lane & 7) + ((lane & 16) >> 1)) * 80 +
                          ((lane & 8) << 1);

    float acc[4][4][4];
#pragma unroll
    for (int i = 0; i < 4; i++)
#pragma unroll
        for (int j = 0; j < 4; j++)
#pragma unroll
            for (int e = 0; e < 4; e++) acc[i][j][e] = 0.0f;

    // prologue: chunk 0 -> stage 0
    stage_load(stB[0],         AhiG, AloG, lda, aBase, 0, tid);
    stage_load(stB[0] + 20480, BhiG, BloG, ldb, bBase, 0, tid);
    CPCOMMIT();

    const int NC = kEnd >> 5;
    for (int c = 0; c < NC; c++) {
        const int st = c & 1;
        if (c + 1 < NC) {
            const int k0 = (c + 1) << 5;
            stage_load(stB[st ^ 1],         AhiG, AloG, lda, aBase, k0, tid);
            stage_load(stB[st ^ 1] + 20480, BhiG, BloG, ldb, bBase, k0, tid);
            CPCOMMIT();
            CPWAIT1();
        } else {
            CPWAIT0();
        }
        __syncthreads();

        const uint32_t aHiB = stB[st],          aLoB = stB[st] + TBYTES;
        const uint32_t bHiB = stB[st] + 20480,  bLoB = stB[st] + 30720;
#pragma unroll
        for (int t = 0; t < 2; t++) {
            const int ks = ksFirst ^ t;
            const uint32_t ko = (uint32_t)ks * 32;    // 16 bf16 = 32 bytes

            uint32_t ah[4][4], al[4][4];
#pragma unroll
            for (int mi = 0; mi < 4; mi++) {
                uint32_t off = aOff + (uint32_t)mi * (16 * 80) + ko;
                ldm_x4(ah[mi], aHiB + off);
                ldm_x4(al[mi], aLoB + off);
            }
            uint32_t bh[4][2], bl[4][2];
#pragma unroll
            for (int n2 = 0; n2 < 2; n2++) {
                uint32_t off = bOff + (uint32_t)n2 * (16 * 80) + ko;
                uint32_t r[4];
                ldm_x4(r, bHiB + off);
                bh[n2 * 2][0] = r[0]; bh[n2 * 2][1] = r[1];
                bh[n2 * 2 + 1][0] = r[2]; bh[n2 * 2 + 1][1] = r[3];
                ldm_x4(r, bLoB + off);
                bl[n2 * 2][0] = r[0]; bl[n2 * 2][1] = r[1];
                bl[n2 * 2 + 1][0] = r[2]; bl[n2 * 2 + 1][1] = r[3];
            }
            // product-major: 16 independent MMAs between accumulator reuse
#pragma unroll
            for (int mi = 0; mi < 4; mi++)
#pragma unroll
                for (int ni = 0; ni < 4; ni++)
                    mma16816(acc[mi][ni], ah[mi], bh[ni]);
#pragma unroll
            for (int mi = 0; mi < 4; mi++)
#pragma unroll
                for (int ni = 0; ni < 4; ni++)
                    mma16816(acc[mi][ni], ah[mi], bl[ni]);
#pragma unroll
            for (int mi = 0; mi < 4; mi++)
#pragma unroll
                for (int ni = 0; ni < 4; ni++)
                    mma16816(acc[mi][ni], al[mi], bh[ni]);
        }
        __syncthreads();
    }

    // ---------------- epilogue ----------------
    const int mBase = warpM + (lane >> 2);
    const int nBase = warpN + (lane & 3) * 2;
    if (EMODE == 0) {
#pragma unroll
        for (int mi = 0; mi < 4; mi++)
#pragma unroll
            for (int ni = 0; ni < 4; ni++) {
                const float* cp = acc[mi][ni];
                int r0 = oRow + mBase + mi * 16;
                int cc = oCol + nBase + ni * 8;
                *(float2*)&C[(size_t)r0 * ldOut + cc]       = make_float2(cp[0], cp[1]);
                *(float2*)&C[(size_t)(r0 + 8) * ldOut + cc] = make_float2(cp[2], cp[3]);
            }
    } else if (EMODE == 2) {
#pragma unroll
        for (int mi = 0; mi < 4; mi++)
#pragma unroll
            for (int ni = 0; ni < 4; ni++) {
                const float* cp = acc[mi][ni];
#pragma unroll
                for (int h = 0; h < 2; h++) {
                    int r0 = oRow + mBase + mi * 16 + h * 8;
                    int cc = oCol + nBase + ni * 8;
                    uint32_t hp, lp;
                    split2c(cp[h * 2], cp[h * 2 + 1], hp, lp);
                    *(uint32_t*)&OHi[(size_t)r0 * ldOut + cc] = hp;
                    *(uint32_t*)&OLo[(size_t)r0 * ldOut + cc] = lp;
                }
            }
    } else {
        // V^T split: (seq=row, e=col) -> Vt[b][e][seq]
#pragma unroll
        for (int mi = 0; mi < 4; mi++)
#pragma unroll
            for (int ni = 0; ni < 4; ni++) {
                const float* cp = acc[mi][ni];
#pragma unroll
                for (int e = 0; e < 4; e++) {
                    int row = oRow + mBase + mi * 16 + (e >> 1) * 8;
                    int col = oCol + nBase + ni * 8 + (e & 1);
                    int b = row >> 11, nloc = row & (NSEQ - 1);
                    float x = cp[e];
                    __nv_bfloat16 hh = __float2bfloat16_rn(x);
                    __nv_bfloat16 ll = __float2bfloat16_rn(x - __bfloat162float(hh));
                    size_t o = ((size_t)b * DOUT + col) * NSEQ + nloc;
                    OHi[o] = hh;
                    OLo[o] = ll;
                }
            }
    }
}

// ---------------- kernels ----------------

__global__ void __launch_bounds__(256) xsplit_kernel(const float* __restrict__ X)
{
    size_t i4 = (size_t)blockIdx.x * 256 + threadIdx.x;
    float4 v = *(const float4*)&X[i4 * 4];
    uint32_t h0, h1, l0, l1;
    split2c(v.x, v.y, h0, l0);
    split2c(v.z, v.w, h1, l1);
    *(uint2*)&g_Xhi[i4 * 4] = make_uint2(h0, h1);
    *(uint2*)&g_Xlo[i4 * 4] = make_uint2(l0, l1);
}

__global__ void __launch_bounds__(256) wsplit_kernel(
    const float* __restrict__ Wq, const float* __restrict__ Wk, const float* __restrict__ Wv)
{
    const int z = blockIdx.z;
    const float* W = (z == 0) ? Wq : (z == 1) ? Wk : Wv;
    __nv_bfloat16* H = g_Wt_hi + (size_t)z * DOUT * DIN;
    __nv_bfloat16* L = g_Wt_lo + (size_t)z * DOUT * DIN;

    __shared__ float t[32][33];
    const int j0 = blockIdx.x * 32;
    const int i0 = blockIdx.y * 32;
    const int tx = threadIdx.x & 31, ty = threadIdx.x >> 5;
#pragma unroll
    for (int k = 0; k < 4; k++)
        t[ty + k * 8][tx] = W[(size_t)(i0 + ty + k * 8) * DOUT + j0 + tx];
    __syncthreads();
#pragma unroll
    for (int k = 0; k < 4; k++) {
        float x = t[tx][ty + k * 8];
        __nv_bfloat16 h = __float2bfloat16_rn(x);
        __nv_bfloat16 l = __float2bfloat16_rn(x - __bfloat162float(h));
        size_t o = (size_t)(j0 + ty + k * 8) * DIN + i0 + tx;
        H[o] = h;
        L[o] = l;
    }
}

// QKV: z=0 -> Q split, z=1 -> K split, z=2 -> V^T split
__global__ void __launch_bounds__(256, 2) qkv_kernel()
{
    const int z = blockIdx.z;
    const __nv_bfloat16* bh = g_Wt_hi + (size_t)z * DOUT * DIN;
    const __nv_bfloat16* bl = g_Wt_lo + (size_t)z * DOUT * DIN;
    const int rowBase = blockIdx.y * 128;
    const int colBase = blockIdx.x * 128;
    if (z == 2)
        gemm_ps<1>(g_Xhi, g_Xlo, DIN, rowBase, bh, bl, DIN, colBase, DIN,
                   nullptr, 0, rowBase, colBase, g_Vt_hi, g_Vt_lo);
    else if (z == 0)
        gemm_ps<2>(g_Xhi, g_Xlo, DIN, rowBase, bh, bl, DIN, colBase, DIN,
                   nullptr, DOUT, rowBase, colBase, g_Qhi, g_Qlo);
    else
        gemm_ps<2>(g_Xhi, g_Xlo, DIN, rowBase, bh, bl, DIN, colBase, DIN,
                   nullptr, DOUT, rowBase, colBase, g_Khi, g_Klo);
}

// Scores S = Q K^T (causal tile skip)
__global__ void __launch_bounds__(256, 2) score_kernel()
{
    const int b = blockIdx.z, qT = blockIdx.y, kT = blockIdx.x;
    if (kT > qT) return;
    gemm_ps<0>(g_Qhi, g_Qlo, DOUT, b * NSEQ + qT * 128,
               g_Khi, g_Klo, DOUT, b * NSEQ + kT * 128, DOUT,
               g_S + (size_t)b * NSEQ * NSEQ, NSEQ, qT * 128, kT * 128,
               nullptr, nullptr);
}

// Causal softmax; writes pre-split bf16 P zero-filled to 128-aligned boundary.
__global__ void __launch_bounds__(256) softmax_kernel()
{
    const int row = blockIdx.x;
    const int b = row >> 11;
    const int q = row & (NSEQ - 1);
    const size_t rb = (size_t)b * NSEQ * NSEQ + (size_t)q * NSEQ;
    const float* s = g_S + rb;

    const int len = q + 1;
    const int alignedOut = (len + 127) & ~127;

    float v[8];
    float m = -1e30f;
#pragma unroll
    for (int i = 0; i < 2; i++) {
        int base = (threadIdx.x + i * 256) * 4;
        if (base < alignedOut) {
            float4 x = *(const float4*)&s[base];
            v[i * 4 + 0] = (base + 0 < len) ? x.x * 0.03125f : -1e30f;
            v[i * 4 + 1] = (base + 1 < len) ? x.y * 0.03125f : -1e30f;
            v[i * 4 + 2] = (base + 2 < len) ? x.z * 0.03125f : -1e30f;
            v[i * 4 + 3] = (base + 3 < len) ? x.w * 0.03125f : -1e30f;
        } else {
            v[i * 4] = v[i * 4 + 1] = v[i * 4 + 2] = v[i * 4 + 3] = -1e30f;
        }
#pragma unroll
        for (int e = 0; e < 4; e++) m = fmaxf(m, v[i * 4 + e]);
    }

    __shared__ float red[256];
    red[threadIdx.x] = m;
    __syncthreads();
#pragma unroll
    for (int off = 128; off > 0; off >>= 1) {
        if (threadIdx.x < off)
            red[threadIdx.x] = fmaxf(red[threadIdx.x], red[threadIdx.x + off]);
        __syncthreads();
    }
    m = red[0];
    __syncthreads();

    float sum = 0.0f;
#pragma unroll
    for (int i = 0; i < 8; i++) {
        float e = __expf(v[i] - m);
        v[i] = e;
        sum += e;
    }
    red[threadIdx.x] = sum;
    __syncthreads();
#pragma unroll
    for (int off = 128; off > 0; off >>= 1) {
        if (threadIdx.x < off)
            red[threadIdx.x] += red[threadIdx.x + off];
        __syncthreads();
    }
    const float inv = 1.0f / red[0];

#pragma unroll
    for (int i = 0; i < 2; i++) {
        int base = (threadIdx.x + i * 256) * 4;
        if (base < alignedOut) {
            float p0 = v[i * 4] * inv, p1 = v[i * 4 + 1] * inv;
            float p2 = v[i * 4 + 2] * inv, p3 = v[i * 4 + 3] * inv;
            uint32_t h0, h1, l0, l1;
            split2c(p0, p1, h0, l0);
            split2c(p2, p3, h1, l1);
            *(uint2*)&g_Phi[rb + base] = make_uint2(h0, h1);
            *(uint2*)&g_Plo[rb + base] = make_uint2(l0, l1);
        }
    }
}

// context = P V, causal K extent.
__global__ void __launch_bounds__(256, 2) pv_kernel(float* __restrict__ out)
{
    const int b = blockIdx.z, qT = blockIdx.y;
    gemm_ps<0>(g_Phi, g_Plo, NSEQ, b * NSEQ + qT * 128,
               g_Vt_hi, g_Vt_lo, NSEQ, b * DOUT + blockIdx.x * 128,
               (qT + 1) * 128,
               out + (size_t)b * NSEQ * DOUT, DOUT, qT * 128, blockIdx.x * 128,
               nullptr, nullptr);
}

// ---------------- launch ----------------
extern "C" void kernel_launch(void* const* d_in, const int* in_sizes, int n_in,
                              void* d_out, int out_size)
{
    (void)in_sizes; (void)n_in; (void)out_size;
    const float* x  = (const float*)d_in[0];
    const float* Wq = (const float*)d_in[1];
    const float* Wk = (const float*)d_in[2];
    const float* Wv = (const float*)d_in[3];
    float* out = (float*)d_out;

    cudaFuncSetAttribute(qkv_kernel,   cudaFuncAttributeMaxDynamicSharedMemorySize, SMEM_SZ);
    cudaFuncSetAttribute(score_kernel, cudaFuncAttributeMaxDynamicSharedMemorySize, SMEM_SZ);
    cudaFuncSetAttribute(pv_kernel,    cudaFuncAttributeMaxDynamicSharedMemorySize, SMEM_SZ);

    xsplit_kernel<<<NTOK * DIN / 1024, 256>>>(x);
    wsplit_kernel<<<dim3(32, 32, 3), 256>>>(Wq, Wk, Wv);
    qkv_kernel<<<dim3(DOUT / 128, NTOK / 128, 3), 256, SMEM_SZ>>>();
    score_kernel<<<dim3(NSEQ / 128, NSEQ / 128, BATCH), 256, SMEM_SZ>>>();
    softmax_kernel<<<BATCH * NSEQ, 256>>>();
    pv_kernel<<<dim3(DOUT / 128, NSEQ / 128, BATCH), 256, SMEM_SZ>>>(out);
}

// round 8
// speedup vs baseline: 2.0878x; 1.0030x over previous
#include <cuda_runtime.h>
#include <cuda_bf16.h>
#include <cstdint>

#define NSEQ 2048
#define DIN  1024
#define DOUT 1024
#define BATCH 8
#define NTOK  (BATCH * NSEQ)   // 16384

// ---------------- device scratch (no allocations allowed) ----------------
__device__ float g_S[(size_t)BATCH * NSEQ * NSEQ];
__device__ __nv_bfloat16 g_Xhi[(size_t)NTOK * DIN];
__device__ __nv_bfloat16 g_Xlo[(size_t)NTOK * DIN];
__device__ __nv_bfloat16 g_Wt_hi[3ull * DOUT * DIN];
__device__ __nv_bfloat16 g_Wt_lo[3ull * DOUT * DIN];
__device__ __nv_bfloat16 g_Qhi[(size_t)NTOK * DOUT];
__device__ __nv_bfloat16 g_Qlo[(size_t)NTOK * DOUT];
__device__ __nv_bfloat16 g_Khi[(size_t)NTOK * DOUT];
__device__ __nv_bfloat16 g_Klo[(size_t)NTOK * DOUT];
__device__ __nv_bfloat16 g_Vt_hi[(size_t)BATCH * DOUT * NSEQ];
__device__ __nv_bfloat16 g_Vt_lo[(size_t)BATCH * DOUT * NSEQ];
__device__ __nv_bfloat16 g_Phi[(size_t)BATCH * NSEQ * NSEQ];
__device__ __nv_bfloat16 g_Plo[(size_t)BATCH * NSEQ * NSEQ];

// ---------------- helpers ----------------
__device__ __forceinline__ uint32_t smem_u32(const void* p) {
    uint32_t a;
    asm("{ .reg .u64 t; cvta.to.shared.u64 t, %1; cvt.u32.u64 %0, t; }" : "=r"(a) : "l"(p));
    return a;
}
__device__ __forceinline__ void ldm_x4(uint32_t r[4], uint32_t addr) {
    asm volatile("ldmatrix.sync.aligned.m8n8.x4.shared.b16 {%0,%1,%2,%3}, [%4];"
                 : "=r"(r[0]), "=r"(r[1]), "=r"(r[2]), "=r"(r[3]) : "r"(addr));
}
__device__ __forceinline__ void mma16816(float* c, const uint32_t* a, const uint32_t* b) {
    asm volatile(
        "mma.sync.aligned.m16n8k16.row.col.f32.bf16.bf16.f32 "
        "{%0,%1,%2,%3}, {%4,%5,%6,%7}, {%8,%9}, {%0,%1,%2,%3};"
        : "+f"(c[0]), "+f"(c[1]), "+f"(c[2]), "+f"(c[3])
        : "r"(a[0]), "r"(a[1]), "r"(a[2]), "r"(a[3]), "r"(b[0]), "r"(b[1]));
}
#define CP16(dst, src) \
    asm volatile("cp.async.cg.shared.global [%0], [%1], 16;" :: "r"(dst), "l"(src))
#define CPCOMMIT() asm volatile("cp.async.commit_group;" ::: "memory")
#define CPWAIT1()  asm volatile("cp.async.wait_group 1;" ::: "memory")
#define CPWAIT0()  asm volatile("cp.async.wait_group 0;" ::: "memory")

__device__ __forceinline__ uint32_t pack2(__nv_bfloat16 a, __nv_bfloat16 b) {
    return (uint32_t)__bfloat16_as_ushort(a) | ((uint32_t)__bfloat16_as_ushort(b) << 16);
}
__device__ __forceinline__ void split2c(float x, float y, uint32_t& hp, uint32_t& lp) {
    __nv_bfloat16 hx = __float2bfloat16_rn(x), hy = __float2bfloat16_rn(y);
    __nv_bfloat16 lx = __float2bfloat16_rn(x - __bfloat162float(hx));
    __nv_bfloat16 ly = __float2bfloat16_rn(y - __bfloat162float(hy));
    hp = pack2(hx, hy);
    lp = pack2(lx, ly);
}

// SMEM tile: 128 rows x 32 k bf16, 80B row stride (conflict-free ldmatrix).
#define TBYTES   10240            // one tile
#define STG      40960            // 4 tiles per stage
#define SMEM_SZ  (2 * STG)        // 81920 B -> 2 CTAs/SM

// issue cp.async for one hi/lo tile pair (128x32) into stage SMEM
__device__ __forceinline__ void stage_load(
    uint32_t sHi, const __nv_bfloat16* __restrict__ hi,
    const __nv_bfloat16* __restrict__ lo, int ld, int base, int k0, int tid)
{
#pragma unroll
    for (int i = 0; i < 2; i++) {
        int idx = tid + i * 256;           // 512 chunks per tile
        int row = idx >> 2;
        int c   = idx & 3;                 // 16B chunk within row
        size_t g = (size_t)(base + row) * ld + k0 + c * 8;
        uint32_t d = sHi + row * 80 + c * 16;
        CP16(d, hi + g);
        CP16(d + TBYTES, lo + g);
    }
}

// ---------------- core GEMM: all operands pre-split bf16 ----------------
// 128x128 CTA tile, 8 warps (2M x 4N), warp tile 64x32, BK=32.
// Inner loop: software-pipelined fragment groups (LDSM hidden under MMAs).
// EMODE: 0 = fp32 C, 1 = split+transposed V^T, 2 = split row-major (Q/K)
template <int EMODE>
__device__ __forceinline__ void gemm_ps(
    const __nv_bfloat16* __restrict__ AhiG, const __nv_bfloat16* __restrict__ AloG,
    int lda, int aBase,
    const __nv_bfloat16* __restrict__ BhiG, const __nv_bfloat16* __restrict__ BloG,
    int ldb, int bBase, int kEnd,
    float* __restrict__ C, int ldOut, int oRow, int oCol,
    __nv_bfloat16* __restrict__ OHi, __nv_bfloat16* __restrict__ OLo)
{
    extern __shared__ char smem[];
    const int tid  = threadIdx.x;
    const int wid  = tid >> 5;
    const int lane = tid & 31;
    const int warpM = (wid >> 2) * 64;
    const int warpN = (wid & 3) * 32;

    const uint32_t sb = smem_u32(smem);
    const uint32_t stB[2] = { sb, sb + STG };

    const uint32_t aOff = (uint32_t)(warpM + (lane & 15)) * 80 + ((lane >> 4) << 4);
    const uint32_t bOff = (uint32_t)(warpN + (lane & 7) + ((lane & 16) >> 1)) * 80 +
                          ((lane & 8) << 1);

    float acc[4][4][4];
#pragma unroll
    for (int i = 0; i < 4; i++)
#pragma unroll
        for (int j = 0; j < 4; j++)
#pragma unroll
            for (int e = 0; e < 4; e++) acc[i][j][e] = 0.0f;

    // prologue: chunk 0 -> stage 0
    stage_load(stB[0],         AhiG, AloG, lda, aBase, 0, tid);
    stage_load(stB[0] + 20480, BhiG, BloG, ldb, bBase, 0, tid);
    CPCOMMIT();

    const int NC = kEnd >> 5;
    for (int c = 0; c < NC; c++) {
        const int st = c & 1;
        if (c + 1 < NC) {
            const int k0 = (c + 1) << 5;
            stage_load(stB[st ^ 1],         AhiG, AloG, lda, aBase, k0, tid);
            stage_load(stB[st ^ 1] + 20480, BhiG, BloG, ldb, bBase, k0, tid);
            CPCOMMIT();
            CPWAIT1();
        } else {
            CPWAIT0();
        }
        __syncthreads();

        const uint32_t aHiB = stB[st],          aLoB = stB[st] + TBYTES;
        const uint32_t bHiB = stB[st] + 20480,  bLoB = stB[st] + 30720;

        uint32_t ah[2][4][4], al[2][4][4], bh[2][4][2], bl[2][4][2];

        // fragment loaders (ks in {0,1} -> byte offset ks*32)
#define LOAD_A(dst, baseB, ko)                                              \
        {                                                                    \
            _Pragma("unroll")                                                \
            for (int mi = 0; mi < 4; mi++)                                   \
                ldm_x4((dst)[mi], (baseB) + aOff + (uint32_t)mi * (16 * 80) + (ko)); \
        }
#define LOAD_B(dst, baseB, ko)                                              \
        {                                                                    \
            _Pragma("unroll")                                                \
            for (int n2 = 0; n2 < 2; n2++) {                                 \
                uint32_t r[4];                                               \
                ldm_x4(r, (baseB) + bOff + (uint32_t)n2 * (16 * 80) + (ko)); \
                (dst)[n2 * 2][0] = r[0]; (dst)[n2 * 2][1] = r[1];            \
                (dst)[n2 * 2 + 1][0] = r[2]; (dst)[n2 * 2 + 1][1] = r[3];    \
            }                                                                \
        }
#define MMA_GRP(af, bf)                                                      \
        {                                                                    \
            _Pragma("unroll")                                                \
            for (int mi = 0; mi < 4; mi++)                                   \
                _Pragma("unroll")                                            \
                for (int ni = 0; ni < 4; ni++)                               \
                    mma16816(acc[mi][ni], (af)[mi], (bf)[ni]);               \
        }

        // software pipeline: each LDSM group issues before an independent MMA group
        LOAD_A(ah[0], aHiB, 0);
        LOAD_B(bh[0], bHiB, 0);
        LOAD_B(bl[0], bLoB, 0);
        MMA_GRP(ah[0], bh[0]);          // hh0  (covers al0 load)
        LOAD_A(al[0], aLoB, 0);
        MMA_GRP(ah[0], bl[0]);          // hl0  (covers ah1/bh1 load)
        LOAD_A(ah[1], aHiB, 32);
        LOAD_B(bh[1], bHiB, 32);
        MMA_GRP(al[0], bh[0]);          // lh0  (covers bl1 load)
        LOAD_B(bl[1], bLoB, 32);
        MMA_GRP(ah[1], bh[1]);          // hh1  (covers al1 load)
        LOAD_A(al[1], aLoB, 32);
        MMA_GRP(ah[1], bl[1]);          // hl1
        MMA_GRP(al[1], bh[1]);          // lh1

#undef LOAD_A
#undef LOAD_B
#undef MMA_GRP
        __syncthreads();
    }

    // ---------------- epilogue ----------------
    const int mBase = warpM + (lane >> 2);
    const int nBase = warpN + (lane & 3) * 2;
    if (EMODE == 0) {
#pragma unroll
        for (int mi = 0; mi < 4; mi++)
#pragma unroll
            for (int ni = 0; ni < 4; ni++) {
                const float* cp = acc[mi][ni];
                int r0 = oRow + mBase + mi * 16;
                int cc = oCol + nBase + ni * 8;
                *(float2*)&C[(size_t)r0 * ldOut + cc]       = make_float2(cp[0], cp[1]);
                *(float2*)&C[(size_t)(r0 + 8) * ldOut + cc] = make_float2(cp[2], cp[3]);
            }
    } else if (EMODE == 2) {
#pragma unroll
        for (int mi = 0; mi < 4; mi++)
#pragma unroll
            for (int ni = 0; ni < 4; ni++) {
                const float* cp = acc[mi][ni];
#pragma unroll
                for (int h = 0; h < 2; h++) {
                    int r0 = oRow + mBase + mi * 16 + h * 8;
                    int cc = oCol + nBase + ni * 8;
                    uint32_t hp, lp;
                    split2c(cp[h * 2], cp[h * 2 + 1], hp, lp);
                    *(uint32_t*)&OHi[(size_t)r0 * ldOut + cc] = hp;
                    *(uint32_t*)&OLo[(size_t)r0 * ldOut + cc] = lp;
                }
            }
    } else {
        // V^T split: (seq=row, e=col) -> Vt[b][e][seq]
#pragma unroll
        for (int mi = 0; mi < 4; mi++)
#pragma unroll
            for (int ni = 0; ni < 4; ni++) {
                const float* cp = acc[mi][ni];
#pragma unroll
                for (int e = 0; e < 4; e++) {
                    int row = oRow + mBase + mi * 16 + (e >> 1) * 8;
                    int col = oCol + nBase + ni * 8 + (e & 1);
                    int b = row >> 11, nloc = row & (NSEQ - 1);
                    float x = cp[e];
                    __nv_bfloat16 hh = __float2bfloat16_rn(x);
                    __nv_bfloat16 ll = __float2bfloat16_rn(x - __bfloat162float(hh));
                    size_t o = ((size_t)b * DOUT + col) * NSEQ + nloc;
                    OHi[o] = hh;
                    OLo[o] = ll;
                }
            }
    }
}

// ---------------- kernels ----------------

__global__ void __launch_bounds__(256) xsplit_kernel(const float* __restrict__ X)
{
    size_t i4 = (size_t)blockIdx.x * 256 + threadIdx.x;
    float4 v = *(const float4*)&X[i4 * 4];
    uint32_t h0, h1, l0, l1;
    split2c(v.x, v.y, h0, l0);
    split2c(v.z, v.w, h1, l1);
    *(uint2*)&g_Xhi[i4 * 4] = make_uint2(h0, h1);
    *(uint2*)&g_Xlo[i4 * 4] = make_uint2(l0, l1);
}

__global__ void __launch_bounds__(256) wsplit_kernel(
    const float* __restrict__ Wq, const float* __restrict__ Wk, const float* __restrict__ Wv)
{
    const int z = blockIdx.z;
    const float* W = (z == 0) ? Wq : (z == 1) ? Wk : Wv;
    __nv_bfloat16* H = g_Wt_hi + (size_t)z * DOUT * DIN;
    __nv_bfloat16* L = g_Wt_lo + (size_t)z * DOUT * DIN;

    __shared__ float t[32][33];
    const int j0 = blockIdx.x * 32;
    const int i0 = blockIdx.y * 32;
    const int tx = threadIdx.x & 31, ty = threadIdx.x >> 5;
#pragma unroll
    for (int k = 0; k < 4; k++)
        t[ty + k * 8][tx] = W[(size_t)(i0 + ty + k * 8) * DOUT + j0 + tx];
    __syncthreads();
#pragma unroll
    for (int k = 0; k < 4; k++) {
        float x = t[tx][ty + k * 8];
        __nv_bfloat16 h = __float2bfloat16_rn(x);
        __nv_bfloat16 l = __float2bfloat16_rn(x - __bfloat162float(h));
        size_t o = (size_t)(j0 + ty + k * 8) * DIN + i0 + tx;
        H[o] = h;
        L[o] = l;
    }
}

// QKV: z=0 -> Q split, z=1 -> K split, z=2 -> V^T split
__global__ void __launch_bounds__(256, 2) qkv_kernel()
{
    const int z = blockIdx.z;
    const __nv_bfloat16* bh = g_Wt_hi + (size_t)z * DOUT * DIN;
    const __nv_bfloat16* bl = g_Wt_lo + (size_t)z * DOUT * DIN;
    const int rowBase = blockIdx.y * 128;
    const int colBase = blockIdx.x * 128;
    if (z == 2)
        gemm_ps<1>(g_Xhi, g_Xlo, DIN, rowBase, bh, bl, DIN, colBase, DIN,
                   nullptr, 0, rowBase, colBase, g_Vt_hi, g_Vt_lo);
    else if (z == 0)
        gemm_ps<2>(g_Xhi, g_Xlo, DIN, rowBase, bh, bl, DIN, colBase, DIN,
                   nullptr, DOUT, rowBase, colBase, g_Qhi, g_Qlo);
    else
        gemm_ps<2>(g_Xhi, g_Xlo, DIN, rowBase, bh, bl, DIN, colBase, DIN,
                   nullptr, DOUT, rowBase, colBase, g_Khi, g_Klo);
}

// Scores S = Q K^T (causal tile skip)
__global__ void __launch_bounds__(256, 2) score_kernel()
{
    const int b = blockIdx.z, qT = blockIdx.y, kT = blockIdx.x;
    if (kT > qT) return;
    gemm_ps<0>(g_Qhi, g_Qlo, DOUT, b * NSEQ + qT * 128,
               g_Khi, g_Klo, DOUT, b * NSEQ + kT * 128, DOUT,
               g_S + (size_t)b * NSEQ * NSEQ, NSEQ, qT * 128, kT * 128,
               nullptr, nullptr);
}

// Causal softmax; writes pre-split bf16 P zero-filled to 128-aligned boundary.
__global__ void __launch_bounds__(256) softmax_kernel()
{
    const int row = blockIdx.x;
    const int b = row >> 11;
    const int q = row & (NSEQ - 1);
    const size_t rb = (size_t)b * NSEQ * NSEQ + (size_t)q * NSEQ;
    const float* s = g_S + rb;

    const int len = q + 1;
    const int alignedOut = (len + 127) & ~127;

    float v[8];
    float m = -1e30f;
#pragma unroll
    for (int i = 0; i < 2; i++) {
        int base = (threadIdx.x + i * 256) * 4;
        if (base < alignedOut) {
            float4 x = *(const float4*)&s[base];
            v[i * 4 + 0] = (base + 0 < len) ? x.x * 0.03125f : -1e30f;
            v[i * 4 + 1] = (base + 1 < len) ? x.y * 0.03125f : -1e30f;
            v[i * 4 + 2] = (base + 2 < len) ? x.z * 0.03125f : -1e30f;
            v[i * 4 + 3] = (base + 3 < len) ? x.w * 0.03125f : -1e30f;
        } else {
            v[i * 4] = v[i * 4 + 1] = v[i * 4 + 2] = v[i * 4 + 3] = -1e30f;
        }
#pragma unroll
        for (int e = 0; e < 4; e++) m = fmaxf(m, v[i * 4 + e]);
    }

    __shared__ float red[256];
    red[threadIdx.x] = m;
    __syncthreads();
#pragma unroll
    for (int off = 128; off > 0; off >>= 1) {
        if (threadIdx.x < off)
            red[threadIdx.x] = fmaxf(red[threadIdx.x], red[threadIdx.x + off]);
        __syncthreads();
    }
    m = red[0];
    __syncthreads();

    float sum = 0.0f;
#pragma unroll
    for (int i = 0; i < 8; i++) {
        float e = __expf(v[i] - m);
        v[i] = e;
        sum += e;
    }
    red[threadIdx.x] = sum;
    __syncthreads();
#pragma unroll
    for (int off = 128; off > 0; off >>= 1) {
        if (threadIdx.x < off)
            red[threadIdx.x] += red[threadIdx.x + off];
        __syncthreads();
    }
    const float inv = 1.0f / red[0];

#pragma unroll
    for (int i = 0; i < 2; i++) {
        int base = (threadIdx.x + i * 256) * 4;
        if (base < alignedOut) {
            float p0 = v[i * 4] * inv, p1 = v[i * 4 + 1] * inv;
            float p2 = v[i * 4 + 2] * inv, p3 = v[i * 4 + 3] * inv;
            uint32_t h0, h1, l0, l1;
            split2c(p0, p1, h0, l0);
            split2c(p2, p3, h1, l1);
            *(uint2*)&g_Phi[rb + base] = make_uint2(h0, h1);
            *(uint2*)&g_Plo[rb + base] = make_uint2(l0, l1);
        }
    }
}

// context = P V, causal K extent.
__global__ void __launch_bounds__(256, 2) pv_kernel(float* __restrict__ out)
{
    const int b = blockIdx.z, qT = blockIdx.y;
    gemm_ps<0>(g_Phi, g_Plo, NSEQ, b * NSEQ + qT * 128,
               g_Vt_hi, g_Vt_lo, NSEQ, b * DOUT + blockIdx.x * 128,
               (qT + 1) * 128,
               out + (size_t)b * NSEQ * DOUT, DOUT, qT * 128, blockIdx.x * 128,
               nullptr, nullptr);
}

// ---------------- launch ----------------
extern "C" void kernel_launch(void* const* d_in, const int* in_sizes, int n_in,
                              void* d_out, int out_size)
{
    (void)in_sizes; (void)n_in; (void)out_size;
    const float* x  = (const float*)d_in[0];
    const float* Wq = (const float*)d_in[1];
    const float* Wk = (const float*)d_in[2];
    const float* Wv = (const float*)d_in[3];
    float* out = (float*)d_out;

    cudaFuncSetAttribute(qkv_kernel,   cudaFuncAttributeMaxDynamicSharedMemorySize, SMEM_SZ);
    cudaFuncSetAttribute(score_kernel, cudaFuncAttributeMaxDynamicSharedMemorySize, SMEM_SZ);
    cudaFuncSetAttribute(pv_kernel,    cudaFuncAttributeMaxDynamicSharedMemorySize, SMEM_SZ);

    xsplit_kernel<<<NTOK * DIN / 1024, 256>>>(x);
    wsplit_kernel<<<dim3(32, 32, 3), 256>>>(Wq, Wk, Wv);
    qkv_kernel<<<dim3(DOUT / 128, NTOK / 128, 3), 256, SMEM_SZ>>>();
    score_kernel<<<dim3(NSEQ / 128, NSEQ / 128, BATCH), 256, SMEM_SZ>>>();
    softmax_kernel<<<BATCH * NSEQ, 256>>>();
    pv_kernel<<<dim3(DOUT / 128, NSEQ / 128, BATCH), 256, SMEM_SZ>>>(out);
}

// round 9
// speedup vs baseline: 2.9029x; 1.3904x over previous
#include <cuda_runtime.h>
#include <cuda_fp16.h>
#include <cstdint>

#define NSEQ 2048
#define DIN  1024
#define DOUT 1024
#define BATCH 8
#define NTOK  (BATCH * NSEQ)   // 16384

// ---------------- device scratch (no allocations allowed) ----------------
__device__ float g_S[(size_t)BATCH * NSEQ * NSEQ];
__device__ __half g_X [(size_t)NTOK * DIN];                 // x rounded to fp16
__device__ __half g_Wh[3ull * DOUT * DIN];                  // W^T hi (fp16)
__device__ __half g_Wl[3ull * DOUT * DIN];                  // W^T lo (fp16)
__device__ __half g_Q [(size_t)NTOK * DOUT];                // Q single fp16
__device__ __half g_Kh[(size_t)NTOK * DOUT];                // K split fp16
__device__ __half g_Kl[(size_t)NTOK * DOUT];
__device__ __half g_Vth[(size_t)BATCH * DOUT * NSEQ];       // V^T split fp16
__device__ __half g_Vtl[(size_t)BATCH * DOUT * NSEQ];
__device__ __half g_P [(size_t)BATCH * NSEQ * NSEQ];        // P single fp16

// ---------------- helpers ----------------
__device__ __forceinline__ uint32_t smem_u32(const void* p) {
    uint32_t a;
    asm("{ .reg .u64 t; cvta.to.shared.u64 t, %1; cvt.u32.u64 %0, t; }" : "=r"(a) : "l"(p));
    return a;
}
__device__ __forceinline__ void ldm_x4(uint32_t r[4], uint32_t addr) {
    asm volatile("ldmatrix.sync.aligned.m8n8.x4.shared.b16 {%0,%1,%2,%3}, [%4];"
                 : "=r"(r[0]), "=r"(r[1]), "=r"(r[2]), "=r"(r[3]) : "r"(addr));
}
__device__ __forceinline__ void mma16816(float* c, const uint32_t* a, const uint32_t* b) {
    asm volatile(
        "mma.sync.aligned.m16n8k16.row.col.f32.f16.f16.f32 "
        "{%0,%1,%2,%3}, {%4,%5,%6,%7}, {%8,%9}, {%0,%1,%2,%3};"
        : "+f"(c[0]), "+f"(c[1]), "+f"(c[2]), "+f"(c[3])
        : "r"(a[0]), "r"(a[1]), "r"(a[2]), "r"(a[3]), "r"(b[0]), "r"(b[1]));
}
#define CP16(dst, src) \
    asm volatile("cp.async.cg.shared.global [%0], [%1], 16;" :: "r"(dst), "l"(src))
#define CPCOMMIT() asm volatile("cp.async.commit_group;" ::: "memory")
#define CPWAIT1()  asm volatile("cp.async.wait_group 1;" ::: "memory")
#define CPWAIT0()  asm volatile("cp.async.wait_group 0;" ::: "memory")

__device__ __forceinline__ uint32_t pack2h(__half a, __half b) {
    return (uint32_t)__half_as_ushort(a) | ((uint32_t)__half_as_ushort(b) << 16);
}
// split x into fp16 hi + fp16 lo (pairwise, packed)
__device__ __forceinline__ void split2h(float x, float y, uint32_t& hp, uint32_t& lp) {
    __half hx = __float2half_rn(x), hy = __float2half_rn(y);
    __half lx = __float2half_rn(x - __half2float(hx));
    __half ly = __float2half_rn(y - __half2float(hy));
    hp = pack2h(hx, hy);
    lp = pack2h(lx, ly);
}

// SMEM tile: 128 rows x 32 k fp16, 80B row stride (conflict-free ldmatrix).
#define TBYTES   10240
#define STG      30720            // A + Bhi + Blo per stage
#define SMEM_SZ  (2 * STG)        // 61440 B -> 2 CTAs/SM (regs permitting)
#define OFF_BH   10240
#define OFF_BL   20480

// cp.async one single tile (128x32 fp16)
__device__ __forceinline__ void stage_load_a(
    uint32_t sA, const __half* __restrict__ A, int ld, int base, int k0, int tid)
{
#pragma unroll
    for (int i = 0; i < 2; i++) {
        int idx = tid + i * 256;
        int row = idx >> 2;
        int c   = idx & 3;
        size_t g = (size_t)(base + row) * ld + k0 + c * 8;
        CP16(sA + row * 80 + c * 16, A + g);
    }
}
// cp.async hi/lo tile pair
__device__ __forceinline__ void stage_load_b(
    uint32_t sHi, const __half* __restrict__ hi, const __half* __restrict__ lo,
    int ld, int base, int k0, int tid)
{
#pragma unroll
    for (int i = 0; i < 2; i++) {
        int idx = tid + i * 256;
        int row = idx >> 2;
        int c   = idx & 3;
        size_t g = (size_t)(base + row) * ld + k0 + c * 8;
        uint32_t d = sHi + row * 80 + c * 16;
        CP16(d, hi + g);
        CP16(d + TBYTES, lo + g);
    }
}

// ---------------- core GEMM: 2-product fp16 emulation ----------------
// C = Ah * (Bh + Bl);  A single fp16, B split fp16.
// 128x128 CTA tile, 8 warps (2M x 4N), warp tile 64x32, BK=32.
// EMODE: 0 = fp32 C, 1 = split fp16 transposed (V^T),
//        2 = single fp16 row-major (Q), 3 = split fp16 row-major (K)
template <int EMODE>
__device__ __forceinline__ void gemm_ps(
    const __half* __restrict__ AG, int lda, int aBase,
    const __half* __restrict__ BhiG, const __half* __restrict__ BloG,
    int ldb, int bBase, int kEnd,
    float* __restrict__ C, int ldOut, int oRow, int oCol,
    __half* __restrict__ OHi, __half* __restrict__ OLo)
{
    extern __shared__ char smem[];
    const int tid  = threadIdx.x;
    const int wid  = tid >> 5;
    const int lane = tid & 31;
    const int warpM = (wid >> 2) * 64;
    const int warpN = (wid & 3) * 32;

    const uint32_t sb = smem_u32(smem);
    const uint32_t stB[2] = { sb, sb + STG };

    const uint32_t aOff = (uint32_t)(warpM + (lane & 15)) * 80 + ((lane >> 4) << 4);
    const uint32_t bOff = (uint32_t)(warpN + (lane & 7) + ((lane & 16) >> 1)) * 80 +
                          ((lane & 8) << 1);

    float acc[4][4][4];
#pragma unroll
    for (int i = 0; i < 4; i++)
#pragma unroll
        for (int j = 0; j < 4; j++)
#pragma unroll
            for (int e = 0; e < 4; e++) acc[i][j][e] = 0.0f;

    // prologue
    stage_load_a(stB[0],          AG,   lda, aBase, 0, tid);
    stage_load_b(stB[0] + OFF_BH, BhiG, BloG, ldb, bBase, 0, tid);
    CPCOMMIT();

    const int NC = kEnd >> 5;
    for (int c = 0; c < NC; c++) {
        const int st = c & 1;
        if (c + 1 < NC) {
            const int k0 = (c + 1) << 5;
            stage_load_a(stB[st ^ 1],          AG,   lda, aBase, k0, tid);
            stage_load_b(stB[st ^ 1] + OFF_BH, BhiG, BloG, ldb, bBase, k0, tid);
            CPCOMMIT();
            CPWAIT1();
        } else {
            CPWAIT0();
        }
        __syncthreads();

        const uint32_t aB  = stB[st];
        const uint32_t bHiB = stB[st] + OFF_BH, bLoB = stB[st] + OFF_BL;

        uint32_t ah[2][4][4], bh[2][4][2], bl[2][4][2];

#define LOAD_A(dst, ko)                                                      \
        {                                                                    \
            _Pragma("unroll")                                                \
            for (int mi = 0; mi < 4; mi++)                                   \
                ldm_x4((dst)[mi], aB + aOff + (uint32_t)mi * (16 * 80) + (ko)); \
        }
#define LOAD_B(dst, baseB, ko)                                               \
        {                                                                    \
            _Pragma("unroll")                                                \
            for (int n2 = 0; n2 < 2; n2++) {                                 \
                uint32_t r[4];                                               \
                ldm_x4(r, (baseB) + bOff + (uint32_t)n2 * (16 * 80) + (ko)); \
                (dst)[n2 * 2][0] = r[0]; (dst)[n2 * 2][1] = r[1];            \
                (dst)[n2 * 2 + 1][0] = r[2]; (dst)[n2 * 2 + 1][1] = r[3];    \
            }                                                                \
        }
#define MMA_GRP(af, bf)                                                      \
        {                                                                    \
            _Pragma("unroll")                                                \
            for (int mi = 0; mi < 4; mi++)                                   \
                _Pragma("unroll")                                            \
                for (int ni = 0; ni < 4; ni++)                               \
                    mma16816(acc[mi][ni], (af)[mi], (bf)[ni]);               \
        }

        LOAD_A(ah[0], 0);
        LOAD_B(bh[0], bHiB, 0);
        LOAD_B(bl[0], bLoB, 0);
        MMA_GRP(ah[0], bh[0]);          // hh0  (covers ah1/bh1 loads)
        LOAD_A(ah[1], 32);
        LOAD_B(bh[1], bHiB, 32);
        MMA_GRP(ah[0], bl[0]);          // hl0  (covers bl1 load)
        LOAD_B(bl[1], bLoB, 32);
        MMA_GRP(ah[1], bh[1]);          // hh1
        MMA_GRP(ah[1], bl[1]);          // hl1

#undef LOAD_A
#undef LOAD_B
#undef MMA_GRP
        __syncthreads();
    }

    // ---------------- epilogue ----------------
    const int mBase = warpM + (lane >> 2);
    const int nBase = warpN + (lane & 3) * 2;
    if (EMODE == 0) {
#pragma unroll
        for (int mi = 0; mi < 4; mi++)
#pragma unroll
            for (int ni = 0; ni < 4; ni++) {
                const float* cp = acc[mi][ni];
                int r0 = oRow + mBase + mi * 16;
                int cc = oCol + nBase + ni * 8;
                *(float2*)&C[(size_t)r0 * ldOut + cc]       = make_float2(cp[0], cp[1]);
                *(float2*)&C[(size_t)(r0 + 8) * ldOut + cc] = make_float2(cp[2], cp[3]);
            }
    } else if (EMODE == 2) {
        // single fp16 row-major (Q)
#pragma unroll
        for (int mi = 0; mi < 4; mi++)
#pragma unroll
            for (int ni = 0; ni < 4; ni++) {
                const float* cp = acc[mi][ni];
#pragma unroll
                for (int h = 0; h < 2; h++) {
                    int r0 = oRow + mBase + mi * 16 + h * 8;
                    int cc = oCol + nBase + ni * 8;
                    uint32_t p = pack2h(__float2half_rn(cp[h * 2]),
                                        __float2half_rn(cp[h * 2 + 1]));
                    *(uint32_t*)&OHi[(size_t)r0 * ldOut + cc] = p;
                }
            }
    } else if (EMODE == 3) {
        // split fp16 row-major (K)
#pragma unroll
        for (int mi = 0; mi < 4; mi++)
#pragma unroll
            for (int ni = 0; ni < 4; ni++) {
                const float* cp = acc[mi][ni];
#pragma unroll
                for (int h = 0; h < 2; h++) {
                    int r0 = oRow + mBase + mi * 16 + h * 8;
                    int cc = oCol + nBase + ni * 8;
                    uint32_t hp, lp;
                    split2h(cp[h * 2], cp[h * 2 + 1], hp, lp);
                    *(uint32_t*)&OHi[(size_t)r0 * ldOut + cc] = hp;
                    *(uint32_t*)&OLo[(size_t)r0 * ldOut + cc] = lp;
                }
            }
    } else {
        // split fp16 transposed (V^T): (seq=row, e=col) -> Vt[b][e][seq]
#pragma unroll
        for (int mi = 0; mi < 4; mi++)
#pragma unroll
            for (int ni = 0; ni < 4; ni++) {
                const float* cp = acc[mi][ni];
#pragma unroll
                for (int e = 0; e < 4; e++) {
                    int row = oRow + mBase + mi * 16 + (e >> 1) * 8;
                    int col = oCol + nBase + ni * 8 + (e & 1);
                    int b = row >> 11, nloc = row & (NSEQ - 1);
                    float x = cp[e];
                    __half hh = __float2half_rn(x);
                    __half ll = __float2half_rn(x - __half2float(hh));
                    size_t o = ((size_t)b * DOUT + col) * NSEQ + nloc;
                    OHi[o] = hh;
                    OLo[o] = ll;
                }
            }
    }
}

// ---------------- kernels ----------------

// Round x to fp16.
__global__ void __launch_bounds__(256) xround_kernel(const float* __restrict__ X)
{
    size_t i4 = (size_t)blockIdx.x * 256 + threadIdx.x;
    float4 v = *(const float4*)&X[i4 * 4];
    uint32_t p0 = pack2h(__float2half_rn(v.x), __float2half_rn(v.y));
    uint32_t p1 = pack2h(__float2half_rn(v.z), __float2half_rn(v.w));
    *(uint2*)&g_X[i4 * 4] = make_uint2(p0, p1);
}

// Transpose + fp16-split weights: Wt[z][dout][din]
__global__ void __launch_bounds__(256) wsplit_kernel(
    const float* __restrict__ Wq, const float* __restrict__ Wk, const float* __restrict__ Wv)
{
    const int z = blockIdx.z;
    const float* W = (z == 0) ? Wq : (z == 1) ? Wk : Wv;
    __half* H = g_Wh + (size_t)z * DOUT * DIN;
    __half* L = g_Wl + (size_t)z * DOUT * DIN;

    __shared__ float t[32][33];
    const int j0 = blockIdx.x * 32;
    const int i0 = blockIdx.y * 32;
    const int tx = threadIdx.x & 31, ty = threadIdx.x >> 5;
#pragma unroll
    for (int k = 0; k < 4; k++)
        t[ty + k * 8][tx] = W[(size_t)(i0 + ty + k * 8) * DOUT + j0 + tx];
    __syncthreads();
#pragma unroll
    for (int k = 0; k < 4; k++) {
        float x = t[tx][ty + k * 8];
        __half h = __float2half_rn(x);
        __half l = __float2half_rn(x - __half2float(h));
        size_t o = (size_t)(j0 + ty + k * 8) * DIN + i0 + tx;
        H[o] = h;
        L[o] = l;
    }
}

// QKV: z=0 -> Q single, z=1 -> K split, z=2 -> V^T split
__global__ void __launch_bounds__(256, 2) qkv_kernel()
{
    const int z = blockIdx.z;
    const __half* bh = g_Wh + (size_t)z * DOUT * DIN;
    const __half* bl = g_Wl + (size_t)z * DOUT * DIN;
    const int rowBase = blockIdx.y * 128;
    const int colBase = blockIdx.x * 128;
    if (z == 2)
        gemm_ps<1>(g_X, DIN, rowBase, bh, bl, DIN, colBase, DIN,
                   nullptr, 0, rowBase, colBase, g_Vth, g_Vtl);
    else if (z == 0)
        gemm_ps<2>(g_X, DIN, rowBase, bh, bl, DIN, colBase, DIN,
                   nullptr, DOUT, rowBase, colBase, g_Q, nullptr);
    else
        gemm_ps<3>(g_X, DIN, rowBase, bh, bl, DIN, colBase, DIN,
                   nullptr, DOUT, rowBase, colBase, g_Kh, g_Kl);
}

// Scores S = Q K^T (causal tile skip)
__global__ void __launch_bounds__(256, 2) score_kernel()
{
    const int b = blockIdx.z, qT = blockIdx.y, kT = blockIdx.x;
    if (kT > qT) return;
    gemm_ps<0>(g_Q, DOUT, b * NSEQ + qT * 128,
               g_Kh, g_Kl, DOUT, b * NSEQ + kT * 128, DOUT,
               g_S + (size_t)b * NSEQ * NSEQ, NSEQ, qT * 128, kT * 128,
               nullptr, nullptr);
}

// Causal softmax; writes single fp16 P zero-filled to 128-aligned boundary.
__global__ void __launch_bounds__(256) softmax_kernel()
{
    const int row = blockIdx.x;
    const int b = row >> 11;
    const int q = row & (NSEQ - 1);
    const size_t rb = (size_t)b * NSEQ * NSEQ + (size_t)q * NSEQ;
    const float* s = g_S + rb;

    const int len = q + 1;
    const int alignedOut = (len + 127) & ~127;

    float v[8];
    float m = -1e30f;
#pragma unroll
    for (int i = 0; i < 2; i++) {
        int base = (threadIdx.x + i * 256) * 4;
        if (base < alignedOut) {
            float4 x = *(const float4*)&s[base];
            v[i * 4 + 0] = (base + 0 < len) ? x.x * 0.03125f : -1e30f;
            v[i * 4 + 1] = (base + 1 < len) ? x.y * 0.03125f : -1e30f;
            v[i * 4 + 2] = (base + 2 < len) ? x.z * 0.03125f : -1e30f;
            v[i * 4 + 3] = (base + 3 < len) ? x.w * 0.03125f : -1e30f;
        } else {
            v[i * 4] = v[i * 4 + 1] = v[i * 4 + 2] = v[i * 4 + 3] = -1e30f;
        }
#pragma unroll
        for (int e = 0; e < 4; e++) m = fmaxf(m, v[i * 4 + e]);
    }

    __shared__ float red[256];
    red[threadIdx.x] = m;
    __syncthreads();
#pragma unroll
    for (int off = 128; off > 0; off >>= 1) {
        if (threadIdx.x < off)
            red[threadIdx.x] = fmaxf(red[threadIdx.x], red[threadIdx.x + off]);
        __syncthreads();
    }
    m = red[0];
    __syncthreads();

    float sum = 0.0f;
#pragma unroll
    for (int i = 0; i < 8; i++) {
        float e = __expf(v[i] - m);
        v[i] = e;
        sum += e;
    }
    red[threadIdx.x] = sum;
    __syncthreads();
#pragma unroll
    for (int off = 128; off > 0; off >>= 1) {
        if (threadIdx.x < off)
            red[threadIdx.x] += red[threadIdx.x + off];
        __syncthreads();
    }
    const float inv = 1.0f / red[0];

#pragma unroll
    for (int i = 0; i < 2; i++) {
        int base = (threadIdx.x + i * 256) * 4;
        if (base < alignedOut) {
            uint32_t p0 = pack2h(__float2half_rn(v[i * 4] * inv),
                                 __float2half_rn(v[i * 4 + 1] * inv));
            uint32_t p1 = pack2h(__float2half_rn(v[i * 4 + 2] * inv),
                                 __float2half_rn(v[i * 4 + 3] * inv));
            *(uint2*)&g_P[rb + base] = make_uint2(p0, p1);
        }
    }
}

// context = P V, causal K extent.
__global__ void __launch_bounds__(256, 2) pv_kernel(float* __restrict__ out)
{
    const int b = blockIdx.z, qT = blockIdx.y;
    gemm_ps<0>(g_P, NSEQ, b * NSEQ + qT * 128,
               g_Vth, g_Vtl, NSEQ, b * DOUT + blockIdx.x * 128,
               (qT + 1) * 128,
               out + (size_t)b * NSEQ * DOUT, DOUT, qT * 128, blockIdx.x * 128,
               nullptr, nullptr);
}

// ---------------- launch ----------------
extern "C" void kernel_launch(void* const* d_in, const int* in_sizes, int n_in,
                              void* d_out, int out_size)
{
    (void)in_sizes; (void)n_in; (void)out_size;
    const float* x  = (const float*)d_in[0];
    const float* Wq = (const float*)d_in[1];
    const float* Wk = (const float*)d_in[2];
    const float* Wv = (const float*)d_in[3];
    float* out = (float*)d_out;

    cudaFuncSetAttribute(qkv_kernel,   cudaFuncAttributeMaxDynamicSharedMemorySize, SMEM_SZ);
    cudaFuncSetAttribute(score_kernel, cudaFuncAttributeMaxDynamicSharedMemorySize, SMEM_SZ);
    cudaFuncSetAttribute(pv_kernel,    cudaFuncAttributeMaxDynamicSharedMemorySize, SMEM_SZ);

    xround_kernel<<<NTOK * DIN / 1024, 256>>>(x);
    wsplit_kernel<<<dim3(32, 32, 3), 256>>>(Wq, Wk, Wv);
    qkv_kernel<<<dim3(DOUT / 128, NTOK / 128, 3), 256, SMEM_SZ>>>();
    score_kernel<<<dim3(NSEQ / 128, NSEQ / 128, BATCH), 256, SMEM_SZ>>>();
    softmax_kernel<<<BATCH * NSEQ, 256>>>();
    pv_kernel<<<dim3(DOUT / 128, NSEQ / 128, BATCH), 256, SMEM_SZ>>>(out);
}

// round 10
// speedup vs baseline: 4.8214x; 1.6609x over previous
#include <cuda_runtime.h>
#include <cuda_fp16.h>
#include <cstdint>

#define NSEQ 2048
#define DIN  1024
#define DOUT 1024
#define BATCH 8
#define NTOK  (BATCH * NSEQ)   // 16384

// ---------------- device scratch (no allocations allowed) ----------------
__device__ float g_S[(size_t)BATCH * NSEQ * NSEQ];
__device__ __half g_X [(size_t)NTOK * DIN];                 // x fp16
__device__ __half g_Wt[3ull * DOUT * DIN];                  // W^T fp16
__device__ __half g_Q [(size_t)NTOK * DOUT];                // Q fp16
__device__ __half g_K [(size_t)NTOK * DOUT];                // K fp16
__device__ __half g_Vt[(size_t)BATCH * DOUT * NSEQ];        // V^T fp16
__device__ __half g_P [(size_t)BATCH * NSEQ * NSEQ];        // P fp16

// ---------------- helpers ----------------
__device__ __forceinline__ uint32_t smem_u32(const void* p) {
    uint32_t a;
    asm("{ .reg .u64 t; cvta.to.shared.u64 t, %1; cvt.u32.u64 %0, t; }" : "=r"(a) : "l"(p));
    return a;
}
__device__ __forceinline__ void ldm_x4(uint32_t r[4], uint32_t addr) {
    asm volatile("ldmatrix.sync.aligned.m8n8.x4.shared.b16 {%0,%1,%2,%3}, [%4];"
                 : "=r"(r[0]), "=r"(r[1]), "=r"(r[2]), "=r"(r[3]) : "r"(addr));
}
__device__ __forceinline__ void mma16816(float* c, const uint32_t* a, const uint32_t* b) {
    asm volatile(
        "mma.sync.aligned.m16n8k16.row.col.f32.f16.f16.f32 "
        "{%0,%1,%2,%3}, {%4,%5,%6,%7}, {%8,%9}, {%0,%1,%2,%3};"
        : "+f"(c[0]), "+f"(c[1]), "+f"(c[2]), "+f"(c[3])
        : "r"(a[0]), "r"(a[1]), "r"(a[2]), "r"(a[3]), "r"(b[0]), "r"(b[1]));
}
#define CP16(dst, src) \
    asm volatile("cp.async.cg.shared.global [%0], [%1], 16;" :: "r"(dst), "l"(src))
#define CPCOMMIT() asm volatile("cp.async.commit_group;" ::: "memory")
#define CPWAIT1()  asm volatile("cp.async.wait_group 1;" ::: "memory")
#define CPWAIT0()  asm volatile("cp.async.wait_group 0;" ::: "memory")

__device__ __forceinline__ uint32_t pack2h(__half a, __half b) {
    return (uint32_t)__half_as_ushort(a) | ((uint32_t)__half_as_ushort(b) << 16);
}

// SMEM tile: 128 rows x 32 k fp16, 80B row stride (conflict-free ldmatrix).
#define TBYTES   10240
#define STG      20480            // A + B per stage
#define SMEM_SZ  (2 * STG)        // 40960 B -> 2 CTAs/SM
#define OFF_B    10240

// cp.async one tile (128x32 fp16)
__device__ __forceinline__ void stage_load(
    uint32_t sT, const __half* __restrict__ T, int ld, int base, int k0, int tid)
{
#pragma unroll
    for (int i = 0; i < 2; i++) {
        int idx = tid + i * 256;
        int row = idx >> 2;
        int c   = idx & 3;
        size_t g = (size_t)(base + row) * ld + k0 + c * 8;
        CP16(sT + row * 80 + c * 16, T + g);
    }
}

// ---------------- core GEMM: plain fp16 x fp16 -> fp32 ----------------
// 128x128 CTA tile, 8 warps (2M x 4N), warp tile 64x32, BK=32.
// EMODE: 0 = fp32 C, 1 = fp16 transposed (V^T), 2 = fp16 row-major (Q/K)
template <int EMODE>
__device__ __forceinline__ void gemm_h(
    const __half* __restrict__ AG, int lda, int aBase,
    const __half* __restrict__ BG, int ldb, int bBase, int kEnd,
    float* __restrict__ C, int ldOut, int oRow, int oCol,
    __half* __restrict__ OH)
{
    extern __shared__ char smem[];
    const int tid  = threadIdx.x;
    const int wid  = tid >> 5;
    const int lane = tid & 31;
    const int warpM = (wid >> 2) * 64;
    const int warpN = (wid & 3) * 32;

    const uint32_t sb = smem_u32(smem);
    const uint32_t stB[2] = { sb, sb + STG };

    const uint32_t aOff = (uint32_t)(warpM + (lane & 15)) * 80 + ((lane >> 4) << 4);
    const uint32_t bOff = (uint32_t)(warpN + (lane & 7) + ((lane & 16) >> 1)) * 80 +
                          ((lane & 8) << 1);

    float acc[4][4][4];
#pragma unroll
    for (int i = 0; i < 4; i++)
#pragma unroll
        for (int j = 0; j < 4; j++)
#pragma unroll
            for (int e = 0; e < 4; e++) acc[i][j][e] = 0.0f;

    // prologue
    stage_load(stB[0],         AG, lda, aBase, 0, tid);
    stage_load(stB[0] + OFF_B, BG, ldb, bBase, 0, tid);
    CPCOMMIT();

    const int NC = kEnd >> 5;
    for (int c = 0; c < NC; c++) {
        const int st = c & 1;
        if (c + 1 < NC) {
            const int k0 = (c + 1) << 5;
            stage_load(stB[st ^ 1],         AG, lda, aBase, k0, tid);
            stage_load(stB[st ^ 1] + OFF_B, BG, ldb, bBase, k0, tid);
            CPCOMMIT();
            CPWAIT1();
        } else {
            CPWAIT0();
        }
        __syncthreads();

        const uint32_t aB = stB[st];
        const uint32_t bB = stB[st] + OFF_B;

        uint32_t ah[2][4][4], bh[2][4][2];

#define LOAD_A(dst, ko)                                                      \
        {                                                                    \
            _Pragma("unroll")                                                \
            for (int mi = 0; mi < 4; mi++)                                   \
                ldm_x4((dst)[mi], aB + aOff + (uint32_t)mi * (16 * 80) + (ko)); \
        }
#define LOAD_B(dst, ko)                                                      \
        {                                                                    \
            _Pragma("unroll")                                                \
            for (int n2 = 0; n2 < 2; n2++) {                                 \
                uint32_t r[4];                                               \
                ldm_x4(r, bB + bOff + (uint32_t)n2 * (16 * 80) + (ko));      \
                (dst)[n2 * 2][0] = r[0]; (dst)[n2 * 2][1] = r[1];            \
                (dst)[n2 * 2 + 1][0] = r[2]; (dst)[n2 * 2 + 1][1] = r[3];    \
            }                                                                \
        }
#define MMA_GRP(af, bf)                                                      \
        {                                                                    \
            _Pragma("unroll")                                                \
            for (int mi = 0; mi < 4; mi++)                                   \
                _Pragma("unroll")                                            \
                for (int ni = 0; ni < 4; ni++)                               \
                    mma16816(acc[mi][ni], (af)[mi], (bf)[ni]);               \
        }

        LOAD_A(ah[0], 0);
        LOAD_B(bh[0], 0);
        MMA_GRP(ah[0], bh[0]);      // covers ks=1 loads
        LOAD_A(ah[1], 32);
        LOAD_B(bh[1], 32);
        MMA_GRP(ah[1], bh[1]);

#undef LOAD_A
#undef LOAD_B
#undef MMA_GRP
        __syncthreads();
    }

    // ---------------- epilogue ----------------
    const int mBase = warpM + (lane >> 2);
    const int nBase = warpN + (lane & 3) * 2;
    if (EMODE == 0) {
#pragma unroll
        for (int mi = 0; mi < 4; mi++)
#pragma unroll
            for (int ni = 0; ni < 4; ni++) {
                const float* cp = acc[mi][ni];
                int r0 = oRow + mBase + mi * 16;
                int cc = oCol + nBase + ni * 8;
                *(float2*)&C[(size_t)r0 * ldOut + cc]       = make_float2(cp[0], cp[1]);
                *(float2*)&C[(size_t)(r0 + 8) * ldOut + cc] = make_float2(cp[2], cp[3]);
            }
    } else if (EMODE == 2) {
        // fp16 row-major (Q, K)
#pragma unroll
        for (int mi = 0; mi < 4; mi++)
#pragma unroll
            for (int ni = 0; ni < 4; ni++) {
                const float* cp = acc[mi][ni];
#pragma unroll
                for (int h = 0; h < 2; h++) {
                    int r0 = oRow + mBase + mi * 16 + h * 8;
                    int cc = oCol + nBase + ni * 8;
                    uint32_t p = pack2h(__float2half_rn(cp[h * 2]),
                                        __float2half_rn(cp[h * 2 + 1]));
                    *(uint32_t*)&OH[(size_t)r0 * ldOut + cc] = p;
                }
            }
    } else {
        // fp16 transposed (V^T): (seq=row, e=col) -> Vt[b][e][seq]
#pragma unroll
        for (int mi = 0; mi < 4; mi++)
#pragma unroll
            for (int ni = 0; ni < 4; ni++) {
                const float* cp = acc[mi][ni];
#pragma unroll
                for (int e = 0; e < 4; e++) {
                    int row = oRow + mBase + mi * 16 + (e >> 1) * 8;
                    int col = oCol + nBase + ni * 8 + (e & 1);
                    int b = row >> 11, nloc = row & (NSEQ - 1);
                    size_t o = ((size_t)b * DOUT + col) * NSEQ + nloc;
                    OH[o] = __float2half_rn(cp[e]);
                }
            }
    }
}

// ---------------- kernels ----------------

// Round x to fp16.
__global__ void __launch_bounds__(256) xround_kernel(const float* __restrict__ X)
{
    size_t i4 = (size_t)blockIdx.x * 256 + threadIdx.x;
    float4 v = *(const float4*)&X[i4 * 4];
    uint32_t p0 = pack2h(__float2half_rn(v.x), __float2half_rn(v.y));
    uint32_t p1 = pack2h(__float2half_rn(v.z), __float2half_rn(v.w));
    *(uint2*)&g_X[i4 * 4] = make_uint2(p0, p1);
}

// Transpose + round weights to fp16: Wt[z][dout][din]
__global__ void __launch_bounds__(256) wtrans_kernel(
    const float* __restrict__ Wq, const float* __restrict__ Wk, const float* __restrict__ Wv)
{
    const int z = blockIdx.z;
    const float* W = (z == 0) ? Wq : (z == 1) ? Wk : Wv;
    __half* T = g_Wt + (size_t)z * DOUT * DIN;

    __shared__ float t[32][33];
    const int j0 = blockIdx.x * 32;
    const int i0 = blockIdx.y * 32;
    const int tx = threadIdx.x & 31, ty = threadIdx.x >> 5;
#pragma unroll
    for (int k = 0; k < 4; k++)
        t[ty + k * 8][tx] = W[(size_t)(i0 + ty + k * 8) * DOUT + j0 + tx];
    __syncthreads();
#pragma unroll
    for (int k = 0; k < 4; k++) {
        size_t o = (size_t)(j0 + ty + k * 8) * DIN + i0 + tx;
        T[o] = __float2half_rn(t[tx][ty + k * 8]);
    }
}

// QKV: z=0 -> Q, z=1 -> K, z=2 -> V^T
__global__ void __launch_bounds__(256, 2) qkv_kernel()
{
    const int z = blockIdx.z;
    const __half* w = g_Wt + (size_t)z * DOUT * DIN;
    const int rowBase = blockIdx.y * 128;
    const int colBase = blockIdx.x * 128;
    if (z == 2)
        gemm_h<1>(g_X, DIN, rowBase, w, DIN, colBase, DIN,
                  nullptr, 0, rowBase, colBase, g_Vt);
    else
        gemm_h<2>(g_X, DIN, rowBase, w, DIN, colBase, DIN,
                  nullptr, DOUT, rowBase, colBase, (z == 0) ? g_Q : g_K);
}

// Scores S = Q K^T (causal tile skip)
__global__ void __launch_bounds__(256, 2) score_kernel()
{
    const int b = blockIdx.z, qT = blockIdx.y, kT = blockIdx.x;
    if (kT > qT) return;
    gemm_h<0>(g_Q, DOUT, b * NSEQ + qT * 128,
              g_K, DOUT, b * NSEQ + kT * 128, DOUT,
              g_S + (size_t)b * NSEQ * NSEQ, NSEQ, qT * 128, kT * 128,
              nullptr);
}

// Causal softmax; writes fp16 P zero-filled to 128-aligned boundary.
__global__ void __launch_bounds__(256) softmax_kernel()
{
    const int row = blockIdx.x;
    const int b = row >> 11;
    const int q = row & (NSEQ - 1);
    const size_t rb = (size_t)b * NSEQ * NSEQ + (size_t)q * NSEQ;
    const float* s = g_S + rb;

    const int len = q + 1;
    const int alignedOut = (len + 127) & ~127;

    float v[8];
    float m = -1e30f;
#pragma unroll
    for (int i = 0; i < 2; i++) {
        int base = (threadIdx.x + i * 256) * 4;
        if (base < alignedOut) {
            float4 x = *(const float4*)&s[base];
            v[i * 4 + 0] = (base + 0 < len) ? x.x * 0.03125f : -1e30f;
            v[i * 4 + 1] = (base + 1 < len) ? x.y * 0.03125f : -1e30f;
            v[i * 4 + 2] = (base + 2 < len) ? x.z * 0.03125f : -1e30f;
            v[i * 4 + 3] = (base + 3 < len) ? x.w * 0.03125f : -1e30f;
        } else {
            v[i * 4] = v[i * 4 + 1] = v[i * 4 + 2] = v[i * 4 + 3] = -1e30f;
        }
#pragma unroll
        for (int e = 0; e < 4; e++) m = fmaxf(m, v[i * 4 + e]);
    }

    __shared__ float red[256];
    red[threadIdx.x] = m;
    __syncthreads();
#pragma unroll
    for (int off = 128; off > 0; off >>= 1) {
        if (threadIdx.x < off)
            red[threadIdx.x] = fmaxf(red[threadIdx.x], red[threadIdx.x + off]);
        __syncthreads();
    }
    m = red[0];
    __syncthreads();

    float sum = 0.0f;
#pragma unroll
    for (int i = 0; i < 8; i++) {
        float e = __expf(v[i] - m);
        v[i] = e;
        sum += e;
    }
    red[threadIdx.x] = sum;
    __syncthreads();
#pragma unroll
    for (int off = 128; off > 0; off >>= 1) {
        if (threadIdx.x < off)
            red[threadIdx.x] += red[threadIdx.x + off];
        __syncthreads();
    }
    const float inv = 1.0f / red[0];

#pragma unroll
    for (int i = 0; i < 2; i++) {
        int base = (threadIdx.x + i * 256) * 4;
        if (base < alignedOut) {
            uint32_t p0 = pack2h(__float2half_rn(v[i * 4] * inv),
                                 __float2half_rn(v[i * 4 + 1] * inv));
            uint32_t p1 = pack2h(__float2half_rn(v[i * 4 + 2] * inv),
                                 __float2half_rn(v[i * 4 + 3] * inv));
            *(uint2*)&g_P[rb + base] = make_uint2(p0, p1);
        }
    }
}

// context = P V, causal K extent.
__global__ void __launch_bounds__(256, 2) pv_kernel(float* __restrict__ out)
{
    const int b = blockIdx.z, qT = blockIdx.y;
    gemm_h<0>(g_P, NSEQ, b * NSEQ + qT * 128,
              g_Vt, NSEQ, b * DOUT + blockIdx.x * 128,
              (qT + 1) * 128,
              out + (size_t)b * NSEQ * DOUT, DOUT, qT * 128, blockIdx.x * 128,
              nullptr);
}

// ---------------- launch ----------------
extern "C" void kernel_launch(void* const* d_in, const int* in_sizes, int n_in,
                              void* d_out, int out_size)
{
    (void)in_sizes; (void)n_in; (void)out_size;
    const float* x  = (const float*)d_in[0];
    const float* Wq = (const float*)d_in[1];
    const float* Wk = (const float*)d_in[2];
    const float* Wv = (const float*)d_in[3];
    float* out = (float*)d_out;

    cudaFuncSetAttribute(qkv_kernel,   cudaFuncAttributeMaxDynamicSharedMemorySize, SMEM_SZ);
    cudaFuncSetAttribute(score_kernel, cudaFuncAttributeMaxDynamicSharedMemorySize, SMEM_SZ);
    cudaFuncSetAttribute(pv_kernel,    cudaFuncAttributeMaxDynamicSharedMemorySize, SMEM_SZ);

    xround_kernel<<<NTOK * DIN / 1024, 256>>>(x);
    wtrans_kernel<<<dim3(32, 32, 3), 256>>>(Wq, Wk, Wv);
    qkv_kernel<<<dim3(DOUT / 128, NTOK / 128, 3), 256, SMEM_SZ>>>();
    score_kernel<<<dim3(NSEQ / 128, NSEQ / 128, BATCH), 256, SMEM_SZ>>>();
    softmax_kernel<<<BATCH * NSEQ, 256>>>();
    pv_kernel<<<dim3(DOUT / 128, NSEQ / 128, BATCH), 256, SMEM_SZ>>>(out);
}